// round 6
// baseline (speedup 1.0000x reference)
#include <cuda_runtime.h>
#include <math.h>
#include <stdint.h>

#define T 2048
#define H 2048
#define NH 32
#define NKV 8
#define HD 64
#define FFN 4096
#define NE 8
#define QKV_N 3072
#define ASSIGN (2*T)

// ---------------- scratch ----------------------------------------------------
__device__ float g_xnorm[T*H];
__device__ float g_qkv[(long)T*QKV_N];
__device__ float g_attn[(long)T*H];
__device__ float g_x2[(long)T*H];     // exact (router)
__device__ float g_x2r[(long)T*H];    // tf32-rounded (GEMM A)
__device__ float g_h1[(long)ASSIGN*FFN];
__device__ float g_h3[(long)ASSIGN*FFN];
__device__ float g_y[(long)ASSIGN*H];
__device__ int   g_counts[NE];
__device__ int   g_offs[NE];
__device__ int   g_fill[NE];
__device__ int   g_perm[ASSIGN];
__device__ float g_permw[ASSIGN];
__device__ int   g_tokpos[ASSIGN];
__device__ int   g_topid[T*2];
__device__ float g_topw[T*2];
// tf32-rounded, TRANSPOSED weight copies (Wt[n][k])
__device__ float g_wqkv_t[(long)QKV_N*H];
__device__ float g_wo_t[(long)H*H];
__device__ float g_w1_t[(long)NE*FFN*H];
__device__ float g_w3_t[(long)NE*FFN*H];
__device__ float g_w2_t[(long)NE*H*FFN];

// ---------------- helpers ------------------------------------------------------
__device__ __forceinline__ uint32_t f2tf(float f) {
    uint32_t u; asm("cvt.rna.tf32.f32 %0, %1;" : "=r"(u) : "f"(f)); return u;
}
__device__ __forceinline__ float f2tff(float f) { return __uint_as_float(f2tf(f)); }
__device__ __forceinline__ void mma_tf32(float* c, const uint32_t* a, const uint32_t* b) {
    asm volatile(
        "mma.sync.aligned.m16n8k8.row.col.f32.tf32.tf32.f32 "
        "{%0,%1,%2,%3},{%4,%5,%6,%7},{%8,%9},{%0,%1,%2,%3};"
        : "+f"(c[0]), "+f"(c[1]), "+f"(c[2]), "+f"(c[3])
        : "r"(a[0]), "r"(a[1]), "r"(a[2]), "r"(a[3]), "r"(b[0]), "r"(b[1]));
}
__device__ __forceinline__ void ldsm4(uint32_t* r, uint32_t addr) {
    asm volatile("ldmatrix.sync.aligned.m8n8.x4.shared.b16 {%0,%1,%2,%3}, [%4];"
        : "=r"(r[0]), "=r"(r[1]), "=r"(r[2]), "=r"(r[3]) : "r"(addr));
}
__device__ __forceinline__ uint32_t smem_u32(const void* p) {
    uint32_t a;
    asm("{ .reg .u64 t; cvta.to.shared.u64 t, %1; cvt.u32.u64 %0, t; }" : "=r"(a) : "l"(p));
    return a;
}
__device__ __forceinline__ void cpasync16(uint32_t dst, const void* src, int szBytes) {
    asm volatile("cp.async.cg.shared.global [%0], [%1], 16, %2;"
        :: "r"(dst), "l"(src), "r"(szBytes) : "memory");
}
__device__ __forceinline__ void cpasync_commit() {
    asm volatile("cp.async.commit_group;" ::: "memory");
}
template<int N>
__device__ __forceinline__ void cpasync_wait() {
    asm volatile("cp.async.wait_group %0;" :: "n"(N) : "memory");
}

// ---------------- transpose + tf32 round pass ----------------------------------
// src: [K][N] row-major, dst: [N][K] row-major (rounded). z = matrix index.
__global__ __launch_bounds__(256) void tround_kernel(
    const float* __restrict__ src, float* __restrict__ dst, int K, int N)
{
    __shared__ float tile[32][33];
    long zoff = (long)blockIdx.z * (long)K * (long)N;
    int n0 = blockIdx.x * 32, k0 = blockIdx.y * 32;
    int tx = threadIdx.x, ty = threadIdx.y;   // 32 x 8
    #pragma unroll
    for (int i = ty; i < 32; i += 8)
        tile[i][tx] = src[zoff + (long)(k0 + i)*N + n0 + tx];
    __syncthreads();
    #pragma unroll
    for (int i = ty; i < 32; i += 8)
        dst[zoff + (long)(n0 + i)*K + k0 + tx] = f2tff(tile[tx][i]);
}

// ---------------- rmsnorm (writes rounded out; optionally exact out2) ----------
__global__ __launch_bounds__(256) void rmsnorm_kernel(
    const float* __restrict__ x, const float* __restrict__ w,
    float* __restrict__ outR, float* __restrict__ outX)
{
    int t = blockIdx.x;
    const float* xr = x + (long)t*H;
    __shared__ float red[256];
    float s = 0.f;
    for (int h = threadIdx.x; h < H; h += 256) { float v = xr[h]; s += v*v; }
    red[threadIdx.x] = s; __syncthreads();
    for (int st = 128; st > 0; st >>= 1) {
        if (threadIdx.x < st) red[threadIdx.x] += red[threadIdx.x+st];
        __syncthreads();
    }
    float inv = rsqrtf(red[0]/(float)H + 1e-5f);
    for (int h = threadIdx.x; h < H; h += 256) {
        float v = xr[h]*inv*w[h];
        outR[(long)t*H + h] = f2tff(v);
        if (outX) outX[(long)t*H + h] = v;
    }
}

// ---------------- tf32 mma.sync GEMM, ldmatrix fragments -----------------------
// CTA 128x256, BK=32, 8 warps (2Mx4N), warp tile 64x64.
// A: [m][k] pre-rounded fp32. B: TRANSPOSED pre-rounded Wt[n][k].
// MODE 0: C = A@B (+addsrc). MODE 1: MoE up (A rows via g_perm).
// MODE 2: MoE down (A rows offs+r, scaled by g_permw).
#define P7 36
#define A7_FLOATS (128*P7)
#define B7_FLOATS (256*P7)
#define G7_SMEM ((2*(A7_FLOATS+B7_FLOATS))*4)

template<int MODE>
__global__ __launch_bounds__(256) void gemm7(
    const float* __restrict__ A, const float* __restrict__ Bt, float* __restrict__ C,
    int M, int N, int K, const float* __restrict__ addsrc, long bStrideZ)
{
    extern __shared__ float sm7[];
    int z = blockIdx.z;
    int mBase = blockIdx.y * 128;
    int nBase = blockIdx.x * 256;
    int Meff = M, rowOff = 0;
    if (MODE == 1 || MODE == 2) {
        Meff = g_counts[z]; rowOff = g_offs[z];
        if (mBase >= Meff) return;
        Bt += (long)z * bStrideZ;
    }

    int tid = threadIdx.x, lane = tid & 31, wid = tid >> 5;
    int mW = (wid >> 2) * 64;
    int nW = (wid & 3) * 64;
    int g  = lane >> 2, t4 = lane & 3;

    uint32_t sAbase = smem_u32(sm7);
    uint32_t sBbase = sAbase + 2u*A7_FLOATS*4u;

    // ---- A staging: rows (tid>>3)+32i, 16B chunk tid&7 ----
    int arow = tid >> 3;
    int ac   = tid & 7;
    const float* aPtr[4]; int aSz[4];
    #pragma unroll
    for (int i = 0; i < 4; i++) {
        int gm = mBase + arow + 32*i;
        bool ok = gm < Meff;
        long r;
        if (MODE == 1)      r = ok ? (long)g_perm[rowOff + gm] : 0;
        else if (MODE == 2) r = (long)(rowOff + (ok ? gm : 0));
        else                r = (long)(ok ? gm : 0);
        aPtr[i] = A + r*(long)K + ac*4;
        aSz[i]  = ok ? 16 : 0;
    }
    // ---- B staging: n-rows (tid>>3)+32i (i<8), 16B chunk tid&7 ----
    const float* bPtr = Bt + (long)(nBase + arow)*K + ac*4;

    float acc[4][8][4];
    #pragma unroll
    for (int mt = 0; mt < 4; mt++)
        #pragma unroll
        for (int nt = 0; nt < 8; nt++)
            #pragma unroll
            for (int q = 0; q < 4; q++) acc[mt][nt][q] = 0.f;

    // ldmatrix per-lane address components
    // A: row = mW + mt*16 + (lane&15), col = s*8 + (lane>>4)*4
    uint32_t aLdOff = ((uint32_t)((mW + (lane & 15))*P7 + (lane >> 4)*4)) * 4u;
    // B: row = nW + ntp*16 + (lane&7) + ((lane&16)?8:0), col = s*8 + ((lane&8)?4:0)
    uint32_t bLdOff = ((uint32_t)((nW + (lane & 7) + ((lane & 16) ? 8 : 0))*P7
                                  + ((lane & 8) ? 4 : 0))) * 4u;

    int KT = K >> 5;

    // ---- stage k-tile 0 ----
    #pragma unroll
    for (int i = 0; i < 4; i++)
        cpasync16(sAbase + ((arow + 32*i)*P7 + ac*4)*4u, aPtr[i], aSz[i]);
    #pragma unroll
    for (int i = 0; i < 8; i++)
        cpasync16(sBbase + ((arow + 32*i)*P7 + ac*4)*4u, bPtr + (long)(32*i)*K, 16);
    cpasync_commit();

    for (int kt = 0; kt < KT; kt++) {
        int buf = kt & 1;
        if (kt + 1 < KT) {
            int k0 = (kt + 1) << 5;
            int nb = buf ^ 1;
            uint32_t aD = sAbase + (uint32_t)nb*A7_FLOATS*4u;
            uint32_t bD = sBbase + (uint32_t)nb*B7_FLOATS*4u;
            #pragma unroll
            for (int i = 0; i < 4; i++)
                cpasync16(aD + ((arow + 32*i)*P7 + ac*4)*4u, aPtr[i] + k0, aSz[i]);
            #pragma unroll
            for (int i = 0; i < 8; i++)
                cpasync16(bD + ((arow + 32*i)*P7 + ac*4)*4u, bPtr + (long)(32*i)*K + k0, 16);
            cpasync_commit();
            cpasync_wait<1>();
        } else {
            cpasync_wait<0>();
        }
        __syncthreads();

        uint32_t aS = sAbase + (uint32_t)buf*A7_FLOATS*4u + aLdOff;
        uint32_t bS = sBbase + (uint32_t)buf*B7_FLOATS*4u + bLdOff;

        #pragma unroll
        for (int s = 0; s < 4; s++) {
            uint32_t af[4][4], bb[4][4];
            #pragma unroll
            for (int mt = 0; mt < 4; mt++)
                ldsm4(af[mt], aS + (uint32_t)(mt*16*P7 + s*8)*4u);
            #pragma unroll
            for (int ntp = 0; ntp < 4; ntp++)
                ldsm4(bb[ntp], bS + (uint32_t)(ntp*16*P7 + s*8)*4u);
            #pragma unroll
            for (int mt = 0; mt < 4; mt++)
                #pragma unroll
                for (int ntp = 0; ntp < 4; ntp++) {
                    mma_tf32(acc[mt][2*ntp+0], af[mt], &bb[ntp][0]);
                    mma_tf32(acc[mt][2*ntp+1], af[mt], &bb[ntp][2]);
                }
        }
        __syncthreads();
    }

    // ---- epilogue ----
    #pragma unroll
    for (int mt = 0; mt < 4; mt++) {
        #pragma unroll
        for (int half = 0; half < 2; half++) {
            int rRel = mW + mt*16 + g + half*8;
            bool ok = (MODE == 0) || (mBase + rRel < Meff);
            if (!ok) continue;
            long crow;
            float scale = 1.f;
            if (MODE == 0) crow = (long)(mBase + rRel);
            else           crow = (long)(rowOff + mBase + rRel);
            if (MODE == 2) scale = g_permw[rowOff + mBase + rRel];
            #pragma unroll
            for (int nt = 0; nt < 8; nt++) {
                int col = nBase + nW + nt*8 + t4*2;
                float v0 = acc[mt][nt][2*half + 0];
                float v1 = acc[mt][nt][2*half + 1];
                if (MODE == 2) { v0 *= scale; v1 *= scale; }
                if (MODE == 0 && addsrc) {
                    v0 += addsrc[crow*N + col];
                    v1 += addsrc[crow*N + col + 1];
                }
                *(float2*)(C + crow*N + col) = make_float2(v0, v1);
            }
        }
    }
}

// ---------------- RoPE --------------------------------------------------------
__global__ __launch_bounds__(256) void rope_kernel(float* __restrict__ qkv)
{
    int t = blockIdx.x;
    float pos = (float)t;
    for (int idx = threadIdx.x; idx < (NH+NKV)*32; idx += 256) {
        int head = idx >> 5;
        int j    = idx & 31;
        int colbase = (head < NH) ? head*HD : (NH*HD + (head-NH)*HD);
        float inv = expf(-((float)(2*j)/(float)HD) * logf(10000.0f));
        float f = pos * inv;
        float c = cosf(f), sn = sinf(f);
        float* p = qkv + (long)t*QKV_N + colbase;
        float x1 = p[j], x2 = p[j+32];
        p[j]    = x1*c - x2*sn;
        p[j+32] = x2*c + x1*sn;
    }
}

// ---------------- tensor-core flash attention (mma.sync) -----------------------
#define AP 68
#define ATTN_SMEM (6*64*AP*4)

__global__ __launch_bounds__(128) void attn_tc_kernel(
    const float* __restrict__ qkv, float* __restrict__ attn)
{
    extern __shared__ uint32_t su[];
    uint32_t* sQh = su;
    uint32_t* sQl = sQh + 64*AP;
    uint32_t* sKh = sQl + 64*AP;
    uint32_t* sKl = sKh + 64*AP;
    uint32_t* sV  = sKl + 64*AP;
    uint32_t* sP  = sV  + 64*AP;

    int h = blockIdx.y, qt = blockIdx.x;
    int kvh = h >> 2;
    int tid = threadIdx.x, lane = tid & 31, w = tid >> 5;
    int g = lane >> 2, t4 = lane & 3;
    int mRow = w*16 + g;

    for (int i = tid; i < 1024; i += 128) {
        int r = i >> 4, d4 = (i & 15) << 2;
        float4 v = *(const float4*)(qkv + (long)(qt*64 + r)*QKV_N + h*HD + d4);
        float vv[4] = {v.x*0.125f, v.y*0.125f, v.z*0.125f, v.w*0.125f};
        #pragma unroll
        for (int j = 0; j < 4; j++) {
            uint32_t hi = f2tf(vv[j]);
            float lo = vv[j] - __uint_as_float(hi);
            sQh[r*AP + d4 + j] = hi;
            sQl[r*AP + d4 + j] = f2tf(lo);
        }
    }

    float m_a = -1e30f, m_b = -1e30f, l_a = 0.f, l_b = 0.f;
    float o[8][4];
    #pragma unroll
    for (int nt = 0; nt < 8; nt++)
        #pragma unroll
        for (int q = 0; q < 4; q++) o[nt][q] = 0.f;

    for (int kt = 0; kt <= qt; kt++) {
        __syncthreads();
        for (int i = tid; i < 1024; i += 128) {
            int r = i >> 4, d4 = (i & 15) << 2;
            const float* kp = qkv + (long)(kt*64 + r)*QKV_N + NH*HD + kvh*HD + d4;
            float4 kv = *(const float4*)kp;
            float4 vv = *(const float4*)(kp + NKV*HD);
            float kk[4] = {kv.x, kv.y, kv.z, kv.w};
            float vf[4] = {vv.x, vv.y, vv.z, vv.w};
            #pragma unroll
            for (int j = 0; j < 4; j++) {
                uint32_t hi = f2tf(kk[j]);
                float lo = kk[j] - __uint_as_float(hi);
                sKh[r*AP + d4 + j] = hi;
                sKl[r*AP + d4 + j] = f2tf(lo);
                sV [r*AP + d4 + j] = f2tf(vf[j]);
            }
        }
        __syncthreads();

        float s[8][4];
        #pragma unroll
        for (int nt = 0; nt < 8; nt++)
            #pragma unroll
            for (int q = 0; q < 4; q++) s[nt][q] = 0.f;

        #pragma unroll
        for (int ks = 0; ks < 8; ks++) {
            uint32_t ah[4], al[4];
            {
                const uint32_t* p = sQh + mRow*AP + ks*8 + t4;
                ah[0]=p[0]; ah[1]=p[8*AP]; ah[2]=p[4]; ah[3]=p[8*AP+4];
                const uint32_t* q2 = sQl + mRow*AP + ks*8 + t4;
                al[0]=q2[0]; al[1]=q2[8*AP]; al[2]=q2[4]; al[3]=q2[8*AP+4];
            }
            #pragma unroll
            for (int nt = 0; nt < 8; nt++) {
                uint32_t bh[2], bl[2];
                const uint32_t* p = sKh + (nt*8 + g)*AP + ks*8 + t4;
                bh[0] = p[0]; bh[1] = p[4];
                const uint32_t* q2 = sKl + (nt*8 + g)*AP + ks*8 + t4;
                bl[0] = q2[0]; bl[1] = q2[4];
                mma_tf32(s[nt], ah, bh);
                mma_tf32(s[nt], ah, bl);
                mma_tf32(s[nt], al, bh);
            }
        }

        if (kt == qt) {
            #pragma unroll
            for (int nt = 0; nt < 8; nt++) {
                int c0 = nt*8 + 2*t4;
                if (c0     > mRow)   s[nt][0] = -1e30f;
                if (c0 + 1 > mRow)   s[nt][1] = -1e30f;
                if (c0     > mRow+8) s[nt][2] = -1e30f;
                if (c0 + 1 > mRow+8) s[nt][3] = -1e30f;
            }
        }

        float rma = -1e30f, rmb = -1e30f;
        #pragma unroll
        for (int nt = 0; nt < 8; nt++) {
            rma = fmaxf(rma, fmaxf(s[nt][0], s[nt][1]));
            rmb = fmaxf(rmb, fmaxf(s[nt][2], s[nt][3]));
        }
        rma = fmaxf(rma, __shfl_xor_sync(0xffffffffu, rma, 1));
        rma = fmaxf(rma, __shfl_xor_sync(0xffffffffu, rma, 2));
        rmb = fmaxf(rmb, __shfl_xor_sync(0xffffffffu, rmb, 1));
        rmb = fmaxf(rmb, __shfl_xor_sync(0xffffffffu, rmb, 2));

        float mna = fmaxf(m_a, rma), mnb = fmaxf(m_b, rmb);
        float suma = 0.f, sumb = 0.f;
        #pragma unroll
        for (int nt = 0; nt < 8; nt++) {
            s[nt][0] = __expf(s[nt][0] - mna); suma += s[nt][0];
            s[nt][1] = __expf(s[nt][1] - mna); suma += s[nt][1];
            s[nt][2] = __expf(s[nt][2] - mnb); sumb += s[nt][2];
            s[nt][3] = __expf(s[nt][3] - mnb); sumb += s[nt][3];
        }
        suma += __shfl_xor_sync(0xffffffffu, suma, 1);
        suma += __shfl_xor_sync(0xffffffffu, suma, 2);
        sumb += __shfl_xor_sync(0xffffffffu, sumb, 1);
        sumb += __shfl_xor_sync(0xffffffffu, sumb, 2);

        float alpa = __expf(m_a - mna), alpb = __expf(m_b - mnb);
        l_a = l_a*alpa + suma; m_a = mna;
        l_b = l_b*alpb + sumb; m_b = mnb;
        #pragma unroll
        for (int nt = 0; nt < 8; nt++) {
            o[nt][0] *= alpa; o[nt][1] *= alpa;
            o[nt][2] *= alpb; o[nt][3] *= alpb;
        }

        #pragma unroll
        for (int nt = 0; nt < 8; nt++) {
            int c0 = nt*8 + 2*t4;
            sP[mRow*AP + c0]       = f2tf(s[nt][0]);
            sP[mRow*AP + c0 + 1]   = f2tf(s[nt][1]);
            sP[(mRow+8)*AP + c0]   = f2tf(s[nt][2]);
            sP[(mRow+8)*AP + c0+1] = f2tf(s[nt][3]);
        }
        __syncwarp();

        #pragma unroll
        for (int ks = 0; ks < 8; ks++) {
            uint32_t ap[4];
            const uint32_t* p = sP + mRow*AP + ks*8 + t4;
            ap[0]=p[0]; ap[1]=p[8*AP]; ap[2]=p[4]; ap[3]=p[8*AP+4];
            #pragma unroll
            for (int nt = 0; nt < 8; nt++) {
                uint32_t bv[2];
                bv[0] = sV[(ks*8 + t4)*AP + nt*8 + g];
                bv[1] = sV[(ks*8 + t4 + 4)*AP + nt*8 + g];
                mma_tf32(o[nt], ap, bv);
            }
        }
    }

    float inva = 1.f / l_a, invb = 1.f / l_b;
    #pragma unroll
    for (int nt = 0; nt < 8; nt++) {
        int col = h*HD + nt*8 + 2*t4;
        long ra = (long)(qt*64 + mRow);
        *(float2*)(attn + ra*H + col) =
            make_float2(f2tff(o[nt][0]*inva), f2tff(o[nt][1]*inva));
        *(float2*)(attn + (ra+8)*H + col) =
            make_float2(f2tff(o[nt][2]*invb), f2tff(o[nt][3]*invb));
    }
}

// ---------------- router / MoE plumbing ---------------------------------------
__global__ void reset_kernel() { if (threadIdx.x < NE) g_counts[threadIdx.x] = 0; }

__global__ __launch_bounds__(256) void router_kernel(
    const float* __restrict__ x, const float* __restrict__ gw)
{
    int t = blockIdx.x;
    const float* xr = x + (long)t*H;
    float p[NE] = {};
    for (int h = threadIdx.x; h < H; h += 256) {
        float xv = xr[h];
        #pragma unroll
        for (int e = 0; e < NE; e++) p[e] += xv * gw[h*NE + e];
    }
    __shared__ float red[NE*256];
    #pragma unroll
    for (int e = 0; e < NE; e++) red[e*256 + threadIdx.x] = p[e];
    __syncthreads();
    for (int st = 128; st > 0; st >>= 1) {
        if (threadIdx.x < st)
            #pragma unroll
            for (int e = 0; e < NE; e++)
                red[e*256+threadIdx.x] += red[e*256+threadIdx.x+st];
        __syncthreads();
    }
    if (threadIdx.x == 0) {
        float l[NE];
        #pragma unroll
        for (int e = 0; e < NE; e++) l[e] = red[e*256];
        int i1 = 0;
        #pragma unroll
        for (int e = 1; e < NE; e++) if (l[e] > l[i1]) i1 = e;
        int i2 = -1;
        #pragma unroll
        for (int e = 0; e < NE; e++) if (e != i1 && (i2 < 0 || l[e] > l[i2])) i2 = e;
        float p2 = expf(l[i2] - l[i1]);
        float inv = 1.f / (1.f + p2);
        g_topid[2*t] = i1;   g_topid[2*t+1] = i2;
        g_topw[2*t]  = inv;  g_topw[2*t+1]  = p2*inv;
        atomicAdd(&g_counts[i1], 1);
        atomicAdd(&g_counts[i2], 1);
    }
}

__global__ void scan_kernel() {
    if (threadIdx.x == 0) {
        int s = 0;
        for (int e = 0; e < NE; e++) { g_offs[e] = s; g_fill[e] = s; s += g_counts[e]; }
    }
}

__global__ void scatter_kernel() {
    int t = blockIdx.x*256 + threadIdx.x;
    if (t >= T) return;
    #pragma unroll
    for (int k = 0; k < 2; k++) {
        int e = g_topid[2*t+k];
        int pos = atomicAdd(&g_fill[e], 1);
        g_perm[pos]  = t;
        g_permw[pos] = g_topw[2*t+k];
        g_tokpos[2*t+k] = pos;
    }
}

__global__ __launch_bounds__(256) void silu_kernel() {
    long n = (long)ASSIGN*FFN;
    for (long i = (long)blockIdx.x*256 + threadIdx.x; i < n; i += (long)gridDim.x*256) {
        float a = g_h1[i];
        g_h1[i] = f2tff((a / (1.f + expf(-a))) * g_h3[i]);
    }
}

__global__ __launch_bounds__(256) void combine_kernel(float* __restrict__ out) {
    int idx = blockIdx.x*256 + threadIdx.x;
    int t = idx >> 11;
    int c = idx & (H-1);
    out[idx] = g_y[(long)g_tokpos[2*t]*H + c] + g_y[(long)g_tokpos[2*t+1]*H + c];
}

// ---------------- launch --------------------------------------------------------
extern "C" void kernel_launch(void* const* d_in, const int* in_sizes, int n_in,
                              void* d_out, int out_size)
{
    const float* hidden = (const float*)d_in[0];
    const float* w_qkv  = (const float*)d_in[2];
    const float* w_o    = (const float*)d_in[3];
    const float* gate_w = (const float*)d_in[4];
    const float* w1     = (const float*)d_in[5];
    const float* w2     = (const float*)d_in[6];
    const float* w3     = (const float*)d_in[7];
    const float* ln1    = (const float*)d_in[8];
    const float* ln2    = (const float*)d_in[9];

    float* out       = (float*)d_out;
    float* final_out = out;
    float* resid_out = out + (long)T*H;

    float *xnorm, *qkvb, *attnb, *x2, *x2r, *h1, *h3, *y;
    float *wqkv_t, *wo_t, *w1t, *w3t, *w2t;
    cudaGetSymbolAddress((void**)&xnorm, g_xnorm);
    cudaGetSymbolAddress((void**)&qkvb,  g_qkv);
    cudaGetSymbolAddress((void**)&attnb, g_attn);
    cudaGetSymbolAddress((void**)&x2,    g_x2);
    cudaGetSymbolAddress((void**)&x2r,   g_x2r);
    cudaGetSymbolAddress((void**)&h1,    g_h1);
    cudaGetSymbolAddress((void**)&h3,    g_h3);
    cudaGetSymbolAddress((void**)&y,     g_y);
    cudaGetSymbolAddress((void**)&wqkv_t, g_wqkv_t);
    cudaGetSymbolAddress((void**)&wo_t,   g_wo_t);
    cudaGetSymbolAddress((void**)&w1t,    g_w1_t);
    cudaGetSymbolAddress((void**)&w3t,    g_w3_t);
    cudaGetSymbolAddress((void**)&w2t,    g_w2_t);

    static bool attrDone = false;
    if (!attrDone) {
        cudaFuncSetAttribute(gemm7<0>, cudaFuncAttributeMaxDynamicSharedMemorySize, G7_SMEM);
        cudaFuncSetAttribute(gemm7<1>, cudaFuncAttributeMaxDynamicSharedMemorySize, G7_SMEM);
        cudaFuncSetAttribute(gemm7<2>, cudaFuncAttributeMaxDynamicSharedMemorySize, G7_SMEM);
        cudaFuncSetAttribute(attn_tc_kernel, cudaFuncAttributeMaxDynamicSharedMemorySize, ATTN_SMEM);
        attrDone = true;
    }

    // ---- weight transpose + tf32 round ----
    { dim3 g(QKV_N/32, H/32, 1);   tround_kernel<<<g,dim3(32,8)>>>(w_qkv, wqkv_t, H, QKV_N); }
    { dim3 g(H/32, H/32, 1);       tround_kernel<<<g,dim3(32,8)>>>(w_o,   wo_t,   H, H); }
    { dim3 g(FFN/32, H/32, NE);    tround_kernel<<<g,dim3(32,8)>>>(w1,    w1t,    H, FFN); }
    { dim3 g(FFN/32, H/32, NE);    tround_kernel<<<g,dim3(32,8)>>>(w3,    w3t,    H, FFN); }
    { dim3 g(H/32, FFN/32, NE);    tround_kernel<<<g,dim3(32,8)>>>(w2,    w2t,    FFN, H); }

    // ---- attention path ----
    rmsnorm_kernel<<<T,256>>>(hidden, ln1, xnorm, nullptr);
    {
        dim3 g(QKV_N/256, T/128, 1);
        gemm7<0><<<g,256,G7_SMEM>>>(xnorm, wqkv_t, qkvb, T, QKV_N, H, nullptr, 0);
    }
    rope_kernel<<<T,256>>>(qkvb);
    {
        dim3 g(T/64, NH, 1);
        attn_tc_kernel<<<g,128,ATTN_SMEM>>>(qkvb, attnb);
    }
    {
        dim3 g(H/256, T/128, 1);
        gemm7<0><<<g,256,G7_SMEM>>>(attnb, wo_t, resid_out, T, H, H, hidden, 0);
    }

    // ---- MoE path ----
    rmsnorm_kernel<<<T,256>>>(resid_out, ln2, x2r, x2);
    reset_kernel<<<1,32>>>();
    router_kernel<<<T,256>>>(x2, gate_w);
    scan_kernel<<<1,1>>>();
    scatter_kernel<<<(T+255)/256,256>>>();
    {
        dim3 g(FFN/256, T/128, NE);
        gemm7<1><<<g,256,G7_SMEM>>>(x2r, w1t, h1, T, FFN, H, nullptr, (long)H*FFN);
        gemm7<1><<<g,256,G7_SMEM>>>(x2r, w3t, h3, T, FFN, H, nullptr, (long)H*FFN);
    }
    silu_kernel<<<4096,256>>>();
    {
        dim3 g(H/256, T/128, NE);
        gemm7<2><<<g,256,G7_SMEM>>>(h1, w2t, y, T, H, FFN, nullptr, (long)FFN*H);
    }
    combine_kernel<<<(T*H)/256,256>>>(final_out);
}

// round 7
// speedup vs baseline: 1.1462x; 1.1462x over previous
#include <cuda_runtime.h>
#include <math.h>
#include <stdint.h>

#define T 2048
#define H 2048
#define NH 32
#define NKV 8
#define HD 64
#define FFN 4096
#define NE 8
#define QKV_N 3072
#define ASSIGN (2*T)

// ---------------- scratch ----------------------------------------------------
__device__ float g_xnorm[T*H];
__device__ float g_qkv[(long)T*QKV_N];
__device__ float g_attn[(long)T*H];
__device__ float g_x2[(long)T*H];     // exact (router)
__device__ float g_x2r[(long)T*H];    // tf32-rounded (GEMM A)
__device__ float g_h1[(long)ASSIGN*FFN];
__device__ float g_h3[(long)ASSIGN*FFN];
__device__ float g_y[(long)ASSIGN*H];
__device__ int   g_counts[NE];
__device__ int   g_offs[NE];
__device__ int   g_fill[NE];
__device__ int   g_perm[ASSIGN];
__device__ float g_permw[ASSIGN];
__device__ int   g_tokpos[ASSIGN];
__device__ int   g_topid[T*2];
__device__ float g_topw[T*2];

// ---------------- helpers ------------------------------------------------------
__device__ __forceinline__ uint32_t f2tf(float f) {
    uint32_t u; asm("cvt.rna.tf32.f32 %0, %1;" : "=r"(u) : "f"(f)); return u;
}
__device__ __forceinline__ float f2tff(float f) { return __uint_as_float(f2tf(f)); }
__device__ __forceinline__ void mma_tf32(float* c, const uint32_t* a, const uint32_t* b) {
    asm volatile(
        "mma.sync.aligned.m16n8k8.row.col.f32.tf32.tf32.f32 "
        "{%0,%1,%2,%3},{%4,%5,%6,%7},{%8,%9},{%0,%1,%2,%3};"
        : "+f"(c[0]), "+f"(c[1]), "+f"(c[2]), "+f"(c[3])
        : "r"(a[0]), "r"(a[1]), "r"(a[2]), "r"(a[3]), "r"(b[0]), "r"(b[1]));
}
__device__ __forceinline__ uint32_t smem_u32(const void* p) {
    uint32_t a;
    asm("{ .reg .u64 t; cvta.to.shared.u64 t, %1; cvt.u32.u64 %0, t; }" : "=r"(a) : "l"(p));
    return a;
}
__device__ __forceinline__ void cpasync16(uint32_t dst, const void* src, int szBytes) {
    asm volatile("cp.async.cg.shared.global [%0], [%1], 16, %2;"
        :: "r"(dst), "l"(src), "r"(szBytes) : "memory");
}
__device__ __forceinline__ void cpasync_commit() {
    asm volatile("cp.async.commit_group;" ::: "memory");
}
template<int N>
__device__ __forceinline__ void cpasync_wait() {
    asm volatile("cp.async.wait_group %0;" :: "n"(N) : "memory");
}

// ---------------- rmsnorm (writes rounded out; optionally exact out2) ----------
__global__ __launch_bounds__(256) void rmsnorm_kernel(
    const float* __restrict__ x, const float* __restrict__ w,
    float* __restrict__ outR, float* __restrict__ outX)
{
    int t = blockIdx.x;
    const float* xr = x + (long)t*H;
    __shared__ float red[256];
    float s = 0.f;
    for (int h = threadIdx.x; h < H; h += 256) { float v = xr[h]; s += v*v; }
    red[threadIdx.x] = s; __syncthreads();
    for (int st = 128; st > 0; st >>= 1) {
        if (threadIdx.x < st) red[threadIdx.x] += red[threadIdx.x+st];
        __syncthreads();
    }
    float inv = rsqrtf(red[0]/(float)H + 1e-5f);
    for (int h = threadIdx.x; h < H; h += 256) {
        float v = xr[h]*inv*w[h];
        outR[(long)t*H + h] = f2tff(v);
        if (outX) outX[(long)t*H + h] = v;
    }
}

// ---------------- tf32 mma.sync GEMM: 128x256 CTA, 64x64 warp tiles ------------
// A: pre-rounded fp32 (cp.async). B: RAW fp32 weights, rounded during staging
// (LDG -> cvt.rna.tf32 -> STS, prefetched across the MMA section).
// MODE 0: C = A@B (+addsrc). MODE 1: MoE up (A rows via g_perm).
// MODE 2: MoE down (A rows offs+r, scaled by g_permw).
#define AP6 36
#define BP6 264
#define A6_FLOATS (128*AP6)
#define B6_FLOATS (32*BP6)
#define G8_SMEM ((2*(A6_FLOATS+B6_FLOATS))*4)

template<int MODE>
__global__ __launch_bounds__(256) void gemm8(
    const float* __restrict__ A, const float* __restrict__ B, float* __restrict__ C,
    int M, int N, int K, const float* __restrict__ addsrc, long bStrideZ)
{
    extern __shared__ float sm8[];
    int z = blockIdx.z;
    int mBase = blockIdx.y * 128;
    int nBase = blockIdx.x * 256;
    int Meff = M, rowOff = 0;
    if (MODE == 1 || MODE == 2) {
        Meff = g_counts[z]; rowOff = g_offs[z];
        if (mBase >= Meff) return;
        B += (long)z * bStrideZ;
    }

    int tid = threadIdx.x, lane = tid & 31, wid = tid >> 5;
    int mW = (wid >> 2) * 64;
    int nW = (wid & 3) * 64;
    int g  = lane >> 2, t4 = lane & 3;

    uint32_t sAbase = smem_u32(sm8);
    float* sB = sm8 + 2*A6_FLOATS;

    // A staging: rows (tid>>3)+32i, 16B chunk (tid&7)
    int arow = tid >> 3;
    int ac   = tid & 7;
    const float* aPtr[4]; int aSz[4];
    #pragma unroll
    for (int i = 0; i < 4; i++) {
        int gm = mBase + arow + 32*i;
        bool ok = gm < Meff;
        long r;
        if (MODE == 1)      r = ok ? (long)g_perm[rowOff + gm] : 0;
        else if (MODE == 2) r = (long)(rowOff + (ok ? gm : 0));
        else                r = (long)(ok ? gm : 0);
        aPtr[i] = A + r*(long)K + ac*4;
        aSz[i]  = ok ? 16 : 0;
    }
    // B staging: k-rows (tid>>6)+4i (i<8), 16B chunk (tid&63)
    int bkk = tid >> 6;
    int bc  = tid & 63;
    const float* bPtr = B + (long)bkk*N + nBase + bc*4;

    float acc[4][8][4];
    #pragma unroll
    for (int mt = 0; mt < 4; mt++)
        #pragma unroll
        for (int nt = 0; nt < 8; nt++)
            #pragma unroll
            for (int q = 0; q < 4; q++) acc[mt][nt][q] = 0.f;

    int KT = K >> 5;
    float4 bR[8];

    // ---- prologue: stage k-tile 0 ----
    #pragma unroll
    for (int i = 0; i < 4; i++)
        cpasync16(sAbase + ((arow + 32*i)*AP6 + ac*4)*4u, aPtr[i], aSz[i]);
    cpasync_commit();
    #pragma unroll
    for (int i = 0; i < 8; i++)
        bR[i] = *(const float4*)(bPtr + (long)(4*i)*N);
    {
        float* d = sB;   // buf 0
        #pragma unroll
        for (int i = 0; i < 8; i++) {
            uint4 u = { f2tf(bR[i].x), f2tf(bR[i].y), f2tf(bR[i].z), f2tf(bR[i].w) };
            *(uint4*)(d + (bkk + 4*i)*BP6 + bc*4) = u;
        }
    }
    cpasync_wait<0>();
    __syncthreads();

    for (int kt = 0; kt < KT; kt++) {
        int buf = kt & 1;
        int nb  = buf ^ 1;
        if (kt + 1 < KT) {
            int k0 = (kt + 1) << 5;
            uint32_t aD = sAbase + (uint32_t)nb*A6_FLOATS*4u;
            #pragma unroll
            for (int i = 0; i < 4; i++)
                cpasync16(aD + ((arow + 32*i)*AP6 + ac*4)*4u, aPtr[i] + k0, aSz[i]);
            cpasync_commit();
            #pragma unroll
            for (int i = 0; i < 8; i++)
                bR[i] = *(const float4*)(bPtr + (long)(k0 + 4*i)*N);
        }

        const uint32_t* as = (const uint32_t*)(sm8 + buf*A6_FLOATS);
        const uint32_t* bs = (const uint32_t*)(sB + buf*B6_FLOATS);

        #pragma unroll
        for (int s = 0; s < 4; s++) {
            uint32_t af[4][4], bf[8][2];
            #pragma unroll
            for (int mt = 0; mt < 4; mt++) {
                const uint32_t* p = as + (mW + mt*16 + g)*AP6 + s*8 + t4;
                af[mt][0] = p[0];
                af[mt][1] = p[8*AP6];
                af[mt][2] = p[4];
                af[mt][3] = p[8*AP6 + 4];
            }
            #pragma unroll
            for (int nt = 0; nt < 8; nt++) {
                const uint32_t* p = bs + (s*8 + t4)*BP6 + nW + nt*8 + g;
                bf[nt][0] = p[0];
                bf[nt][1] = p[4*BP6];
            }
            #pragma unroll
            for (int mt = 0; mt < 4; mt++)
                #pragma unroll
                for (int nt = 0; nt < 8; nt++)
                    mma_tf32(acc[mt][nt], af[mt], bf[nt]);
        }

        if (kt + 1 < KT) {
            float* d = sB + nb*B6_FLOATS;
            #pragma unroll
            for (int i = 0; i < 8; i++) {
                uint4 u = { f2tf(bR[i].x), f2tf(bR[i].y), f2tf(bR[i].z), f2tf(bR[i].w) };
                *(uint4*)(d + (bkk + 4*i)*BP6 + bc*4) = u;
            }
            cpasync_wait<0>();
        }
        __syncthreads();
    }

    // ---- epilogue ----
    #pragma unroll
    for (int mt = 0; mt < 4; mt++) {
        #pragma unroll
        for (int half = 0; half < 2; half++) {
            int rRel = mW + mt*16 + g + half*8;
            bool ok = (MODE == 0) || (mBase + rRel < Meff);
            if (!ok) continue;
            long crow;
            float scale = 1.f;
            if (MODE == 0) crow = (long)(mBase + rRel);
            else           crow = (long)(rowOff + mBase + rRel);
            if (MODE == 2) scale = g_permw[rowOff + mBase + rRel];
            #pragma unroll
            for (int nt = 0; nt < 8; nt++) {
                int col = nBase + nW + nt*8 + t4*2;
                float v0 = acc[mt][nt][2*half + 0];
                float v1 = acc[mt][nt][2*half + 1];
                if (MODE == 2) { v0 *= scale; v1 *= scale; }
                if (MODE == 0 && addsrc) {
                    v0 += addsrc[crow*N + col];
                    v1 += addsrc[crow*N + col + 1];
                }
                *(float2*)(C + crow*N + col) = make_float2(v0, v1);
            }
        }
    }
}

// ---------------- RoPE --------------------------------------------------------
__global__ __launch_bounds__(256) void rope_kernel(float* __restrict__ qkv)
{
    int t = blockIdx.x;
    float pos = (float)t;
    for (int idx = threadIdx.x; idx < (NH+NKV)*32; idx += 256) {
        int head = idx >> 5;
        int j    = idx & 31;
        int colbase = (head < NH) ? head*HD : (NH*HD + (head-NH)*HD);
        float inv = expf(-((float)(2*j)/(float)HD) * logf(10000.0f));
        float f = pos * inv;
        float c = cosf(f), sn = sinf(f);
        float* p = qkv + (long)t*QKV_N + colbase;
        float x1 = p[j], x2 = p[j+32];
        p[j]    = x1*c - x2*sn;
        p[j+32] = x2*c + x1*sn;
    }
}

// ---------------- tensor-core flash attention (mma.sync) -----------------------
#define AP 68
#define ATTN_SMEM (6*64*AP*4)

__global__ __launch_bounds__(128) void attn_tc_kernel(
    const float* __restrict__ qkv, float* __restrict__ attn)
{
    extern __shared__ uint32_t su[];
    uint32_t* sQh = su;
    uint32_t* sQl = sQh + 64*AP;
    uint32_t* sKh = sQl + 64*AP;
    uint32_t* sKl = sKh + 64*AP;
    uint32_t* sV  = sKl + 64*AP;
    uint32_t* sP  = sV  + 64*AP;

    int h = blockIdx.y, qt = blockIdx.x;
    int kvh = h >> 2;
    int tid = threadIdx.x, lane = tid & 31, w = tid >> 5;
    int g = lane >> 2, t4 = lane & 3;
    int mRow = w*16 + g;

    for (int i = tid; i < 1024; i += 128) {
        int r = i >> 4, d4 = (i & 15) << 2;
        float4 v = *(const float4*)(qkv + (long)(qt*64 + r)*QKV_N + h*HD + d4);
        float vv[4] = {v.x*0.125f, v.y*0.125f, v.z*0.125f, v.w*0.125f};
        #pragma unroll
        for (int j = 0; j < 4; j++) {
            uint32_t hi = f2tf(vv[j]);
            float lo = vv[j] - __uint_as_float(hi);
            sQh[r*AP + d4 + j] = hi;
            sQl[r*AP + d4 + j] = f2tf(lo);
        }
    }

    float m_a = -1e30f, m_b = -1e30f, l_a = 0.f, l_b = 0.f;
    float o[8][4];
    #pragma unroll
    for (int nt = 0; nt < 8; nt++)
        #pragma unroll
        for (int q = 0; q < 4; q++) o[nt][q] = 0.f;

    for (int kt = 0; kt <= qt; kt++) {
        __syncthreads();
        for (int i = tid; i < 1024; i += 128) {
            int r = i >> 4, d4 = (i & 15) << 2;
            const float* kp = qkv + (long)(kt*64 + r)*QKV_N + NH*HD + kvh*HD + d4;
            float4 kv = *(const float4*)kp;
            float4 vv = *(const float4*)(kp + NKV*HD);
            float kk[4] = {kv.x, kv.y, kv.z, kv.w};
            float vf[4] = {vv.x, vv.y, vv.z, vv.w};
            #pragma unroll
            for (int j = 0; j < 4; j++) {
                uint32_t hi = f2tf(kk[j]);
                float lo = kk[j] - __uint_as_float(hi);
                sKh[r*AP + d4 + j] = hi;
                sKl[r*AP + d4 + j] = f2tf(lo);
                sV [r*AP + d4 + j] = f2tf(vf[j]);
            }
        }
        __syncthreads();

        float s[8][4];
        #pragma unroll
        for (int nt = 0; nt < 8; nt++)
            #pragma unroll
            for (int q = 0; q < 4; q++) s[nt][q] = 0.f;

        #pragma unroll
        for (int ks = 0; ks < 8; ks++) {
            uint32_t ah[4], al[4];
            {
                const uint32_t* p = sQh + mRow*AP + ks*8 + t4;
                ah[0]=p[0]; ah[1]=p[8*AP]; ah[2]=p[4]; ah[3]=p[8*AP+4];
                const uint32_t* q2 = sQl + mRow*AP + ks*8 + t4;
                al[0]=q2[0]; al[1]=q2[8*AP]; al[2]=q2[4]; al[3]=q2[8*AP+4];
            }
            #pragma unroll
            for (int nt = 0; nt < 8; nt++) {
                uint32_t bh[2], bl[2];
                const uint32_t* p = sKh + (nt*8 + g)*AP + ks*8 + t4;
                bh[0] = p[0]; bh[1] = p[4];
                const uint32_t* q2 = sKl + (nt*8 + g)*AP + ks*8 + t4;
                bl[0] = q2[0]; bl[1] = q2[4];
                mma_tf32(s[nt], ah, bh);
                mma_tf32(s[nt], ah, bl);
                mma_tf32(s[nt], al, bh);
            }
        }

        if (kt == qt) {
            #pragma unroll
            for (int nt = 0; nt < 8; nt++) {
                int c0 = nt*8 + 2*t4;
                if (c0     > mRow)   s[nt][0] = -1e30f;
                if (c0 + 1 > mRow)   s[nt][1] = -1e30f;
                if (c0     > mRow+8) s[nt][2] = -1e30f;
                if (c0 + 1 > mRow+8) s[nt][3] = -1e30f;
            }
        }

        float rma = -1e30f, rmb = -1e30f;
        #pragma unroll
        for (int nt = 0; nt < 8; nt++) {
            rma = fmaxf(rma, fmaxf(s[nt][0], s[nt][1]));
            rmb = fmaxf(rmb, fmaxf(s[nt][2], s[nt][3]));
        }
        rma = fmaxf(rma, __shfl_xor_sync(0xffffffffu, rma, 1));
        rma = fmaxf(rma, __shfl_xor_sync(0xffffffffu, rma, 2));
        rmb = fmaxf(rmb, __shfl_xor_sync(0xffffffffu, rmb, 1));
        rmb = fmaxf(rmb, __shfl_xor_sync(0xffffffffu, rmb, 2));

        float mna = fmaxf(m_a, rma), mnb = fmaxf(m_b, rmb);
        float suma = 0.f, sumb = 0.f;
        #pragma unroll
        for (int nt = 0; nt < 8; nt++) {
            s[nt][0] = __expf(s[nt][0] - mna); suma += s[nt][0];
            s[nt][1] = __expf(s[nt][1] - mna); suma += s[nt][1];
            s[nt][2] = __expf(s[nt][2] - mnb); sumb += s[nt][2];
            s[nt][3] = __expf(s[nt][3] - mnb); sumb += s[nt][3];
        }
        suma += __shfl_xor_sync(0xffffffffu, suma, 1);
        suma += __shfl_xor_sync(0xffffffffu, suma, 2);
        sumb += __shfl_xor_sync(0xffffffffu, sumb, 1);
        sumb += __shfl_xor_sync(0xffffffffu, sumb, 2);

        float alpa = __expf(m_a - mna), alpb = __expf(m_b - mnb);
        l_a = l_a*alpa + suma; m_a = mna;
        l_b = l_b*alpb + sumb; m_b = mnb;
        #pragma unroll
        for (int nt = 0; nt < 8; nt++) {
            o[nt][0] *= alpa; o[nt][1] *= alpa;
            o[nt][2] *= alpb; o[nt][3] *= alpb;
        }

        #pragma unroll
        for (int nt = 0; nt < 8; nt++) {
            int c0 = nt*8 + 2*t4;
            sP[mRow*AP + c0]       = f2tf(s[nt][0]);
            sP[mRow*AP + c0 + 1]   = f2tf(s[nt][1]);
            sP[(mRow+8)*AP + c0]   = f2tf(s[nt][2]);
            sP[(mRow+8)*AP + c0+1] = f2tf(s[nt][3]);
        }
        __syncwarp();

        #pragma unroll
        for (int ks = 0; ks < 8; ks++) {
            uint32_t ap[4];
            const uint32_t* p = sP + mRow*AP + ks*8 + t4;
            ap[0]=p[0]; ap[1]=p[8*AP]; ap[2]=p[4]; ap[3]=p[8*AP+4];
            #pragma unroll
            for (int nt = 0; nt < 8; nt++) {
                uint32_t bv[2];
                bv[0] = sV[(ks*8 + t4)*AP + nt*8 + g];
                bv[1] = sV[(ks*8 + t4 + 4)*AP + nt*8 + g];
                mma_tf32(o[nt], ap, bv);
            }
        }
    }

    float inva = 1.f / l_a, invb = 1.f / l_b;
    #pragma unroll
    for (int nt = 0; nt < 8; nt++) {
        int col = h*HD + nt*8 + 2*t4;
        long ra = (long)(qt*64 + mRow);
        *(float2*)(attn + ra*H + col) =
            make_float2(f2tff(o[nt][0]*inva), f2tff(o[nt][1]*inva));
        *(float2*)(attn + (ra+8)*H + col) =
            make_float2(f2tff(o[nt][2]*invb), f2tff(o[nt][3]*invb));
    }
}

// ---------------- router / MoE plumbing ---------------------------------------
__global__ void reset_kernel() { if (threadIdx.x < NE) g_counts[threadIdx.x] = 0; }

__global__ __launch_bounds__(256) void router_kernel(
    const float* __restrict__ x, const float* __restrict__ gw)
{
    int t = blockIdx.x;
    const float* xr = x + (long)t*H;
    float p[NE] = {};
    for (int h = threadIdx.x; h < H; h += 256) {
        float xv = xr[h];
        #pragma unroll
        for (int e = 0; e < NE; e++) p[e] += xv * gw[h*NE + e];
    }
    __shared__ float red[NE*256];
    #pragma unroll
    for (int e = 0; e < NE; e++) red[e*256 + threadIdx.x] = p[e];
    __syncthreads();
    for (int st = 128; st > 0; st >>= 1) {
        if (threadIdx.x < st)
            #pragma unroll
            for (int e = 0; e < NE; e++)
                red[e*256+threadIdx.x] += red[e*256+threadIdx.x+st];
        __syncthreads();
    }
    if (threadIdx.x == 0) {
        float l[NE];
        #pragma unroll
        for (int e = 0; e < NE; e++) l[e] = red[e*256];
        int i1 = 0;
        #pragma unroll
        for (int e = 1; e < NE; e++) if (l[e] > l[i1]) i1 = e;
        int i2 = -1;
        #pragma unroll
        for (int e = 0; e < NE; e++) if (e != i1 && (i2 < 0 || l[e] > l[i2])) i2 = e;
        float p2 = expf(l[i2] - l[i1]);
        float inv = 1.f / (1.f + p2);
        g_topid[2*t] = i1;   g_topid[2*t+1] = i2;
        g_topw[2*t]  = inv;  g_topw[2*t+1]  = p2*inv;
        atomicAdd(&g_counts[i1], 1);
        atomicAdd(&g_counts[i2], 1);
    }
}

__global__ void scan_kernel() {
    if (threadIdx.x == 0) {
        int s = 0;
        for (int e = 0; e < NE; e++) { g_offs[e] = s; g_fill[e] = s; s += g_counts[e]; }
    }
}

__global__ void scatter_kernel() {
    int t = blockIdx.x*256 + threadIdx.x;
    if (t >= T) return;
    #pragma unroll
    for (int k = 0; k < 2; k++) {
        int e = g_topid[2*t+k];
        int pos = atomicAdd(&g_fill[e], 1);
        g_perm[pos]  = t;
        g_permw[pos] = g_topw[2*t+k];
        g_tokpos[2*t+k] = pos;
    }
}

__global__ __launch_bounds__(256) void silu_kernel() {
    long n = (long)ASSIGN*FFN;
    for (long i = (long)blockIdx.x*256 + threadIdx.x; i < n; i += (long)gridDim.x*256) {
        float a = g_h1[i];
        g_h1[i] = f2tff((a / (1.f + expf(-a))) * g_h3[i]);
    }
}

__global__ __launch_bounds__(256) void combine_kernel(float* __restrict__ out) {
    int idx = blockIdx.x*256 + threadIdx.x;
    int t = idx >> 11;
    int c = idx & (H-1);
    out[idx] = g_y[(long)g_tokpos[2*t]*H + c] + g_y[(long)g_tokpos[2*t+1]*H + c];
}

// ---------------- launch --------------------------------------------------------
extern "C" void kernel_launch(void* const* d_in, const int* in_sizes, int n_in,
                              void* d_out, int out_size)
{
    const float* hidden = (const float*)d_in[0];
    const float* w_qkv  = (const float*)d_in[2];
    const float* w_o    = (const float*)d_in[3];
    const float* gate_w = (const float*)d_in[4];
    const float* w1     = (const float*)d_in[5];
    const float* w2     = (const float*)d_in[6];
    const float* w3     = (const float*)d_in[7];
    const float* ln1    = (const float*)d_in[8];
    const float* ln2    = (const float*)d_in[9];

    float* out       = (float*)d_out;
    float* final_out = out;
    float* resid_out = out + (long)T*H;

    float *xnorm, *qkvb, *attnb, *x2, *x2r, *h1, *h3, *y;
    cudaGetSymbolAddress((void**)&xnorm, g_xnorm);
    cudaGetSymbolAddress((void**)&qkvb,  g_qkv);
    cudaGetSymbolAddress((void**)&attnb, g_attn);
    cudaGetSymbolAddress((void**)&x2,    g_x2);
    cudaGetSymbolAddress((void**)&x2r,   g_x2r);
    cudaGetSymbolAddress((void**)&h1,    g_h1);
    cudaGetSymbolAddress((void**)&h3,    g_h3);
    cudaGetSymbolAddress((void**)&y,     g_y);

    static bool attrDone = false;
    if (!attrDone) {
        cudaFuncSetAttribute(gemm8<0>, cudaFuncAttributeMaxDynamicSharedMemorySize, G8_SMEM);
        cudaFuncSetAttribute(gemm8<1>, cudaFuncAttributeMaxDynamicSharedMemorySize, G8_SMEM);
        cudaFuncSetAttribute(gemm8<2>, cudaFuncAttributeMaxDynamicSharedMemorySize, G8_SMEM);
        cudaFuncSetAttribute(attn_tc_kernel, cudaFuncAttributeMaxDynamicSharedMemorySize, ATTN_SMEM);
        attrDone = true;
    }

    // ---- attention path ----
    rmsnorm_kernel<<<T,256>>>(hidden, ln1, xnorm, nullptr);
    {
        dim3 g(QKV_N/256, T/128, 1);
        gemm8<0><<<g,256,G8_SMEM>>>(xnorm, w_qkv, qkvb, T, QKV_N, H, nullptr, 0);
    }
    rope_kernel<<<T,256>>>(qkvb);
    {
        dim3 g(T/64, NH, 1);
        attn_tc_kernel<<<g,128,ATTN_SMEM>>>(qkvb, attnb);
    }
    {
        dim3 g(H/256, T/128, 1);
        gemm8<0><<<g,256,G8_SMEM>>>(attnb, w_o, resid_out, T, H, H, hidden, 0);
    }

    // ---- MoE path ----
    rmsnorm_kernel<<<T,256>>>(resid_out, ln2, x2r, x2);
    reset_kernel<<<1,32>>>();
    router_kernel<<<T,256>>>(x2, gate_w);
    scan_kernel<<<1,1>>>();
    scatter_kernel<<<(T+255)/256,256>>>();
    {
        dim3 g(FFN/256, T/128, NE);
        gemm8<1><<<g,256,G8_SMEM>>>(x2r, w1, h1, T, FFN, H, nullptr, (long)H*FFN);
        gemm8<1><<<g,256,G8_SMEM>>>(x2r, w3, h3, T, FFN, H, nullptr, (long)H*FFN);
    }
    silu_kernel<<<4096,256>>>();
    {
        dim3 g(H/256, T/128, NE);
        gemm8<2><<<g,256,G8_SMEM>>>(h1, w2, y, T, H, FFN, nullptr, (long)FFN*H);
    }
    combine_kernel<<<(T*H)/256,256>>>(final_out);
}